// round 8
// baseline (speedup 1.0000x reference)
#include <cuda_runtime.h>

#define N_NODES 100000
#define E_EDGES 1600000
#define IN_DIMC 128
#define HID 64
#define EMB 32

// ---------------- device scratch (no allocations allowed) ----------------
__device__ int   g_deg[N_NODES];
__device__ float g_dinv[N_NODES];
__device__ float g_hs  [(size_t)N_NODES * HID];  // (x@W1) * dinv[row]
__device__ float g_acc1[(size_t)N_NODES * HID];  // scatter accumulator L1
__device__ float g_zs  [(size_t)N_NODES * EMB];  // (h1@W2) * dinv[row]
__device__ float g_acc2[(size_t)N_NODES * EMB];  // scatter accumulator L2

// one-instruction 16B global f32 reduction (sm_90+)
__device__ __forceinline__ void red_add_v4(float* addr, float4 v) {
    asm volatile("red.global.add.v4.f32 [%0], {%1, %2, %3, %4};"
                 :: "l"(addr), "f"(v.x), "f"(v.y), "f"(v.z), "f"(v.w)
                 : "memory");
}

__device__ __forceinline__ int clampN(int v) {
    return ((unsigned)v >= N_NODES) ? 0 : v;   // defensive: rel_err not crash
}

// ---------------- degree / dinv prep ----------------
__global__ void k_init_deg() {
    int i = blockIdx.x * blockDim.x + threadIdx.x;
    if (i < N_NODES) g_deg[i] = 1;  // self-loop
}

__global__ void k_edges(const int* __restrict__ ei) {
    int i = blockIdx.x * blockDim.x + threadIdx.x;
    if (i < E_EDGES) {
        int t = clampN(ei[E_EDGES + i]);
        atomicAdd(&g_deg[t], 1);
    }
}

__global__ void k_dinv() {
    int i = blockIdx.x * blockDim.x + threadIdx.x;
    if (i < N_NODES) g_dinv[i] = rsqrtf((float)g_deg[i]);
}

// ---------------- GEMM1: hs = (x @ W1) * dinv[row]; acc1 = hs ----------------
// tile 128 rows x 64 cols, threads (16,16)=256, 8x4 micro-tile
// a: scalar broadcast LDS, b: LDS.128 -> 1.5 B/FMA; ~70 regs -> occ >= 50%
__global__ void k_gemm1(const float* __restrict__ x, const float* __restrict__ W1) {
    __shared__ float xs[128][68];    // [row][k], padded
    __shared__ float ws[64][68];     // [k][col], padded
    int row0 = blockIdx.x * 128;
    int tx = threadIdx.x;            // 0..15 -> cols tx*4..+3
    int ty = threadIdx.y;            // 0..15 -> rows ty*8..+7
    int tid = ty * 16 + tx;
    float acc[8][4] = {};

    for (int kb = 0; kb < IN_DIMC; kb += 64) {
        // xs: 128 rows x 16 float4 = 2048 float4, 8 per thread, coalesced
        #pragma unroll
        for (int i = 0; i < 8; i++) {
            int lin = tid + i * 256;
            int r = lin >> 4, k4 = lin & 15;
            float4 v = make_float4(0.f, 0.f, 0.f, 0.f);
            int row = row0 + r;
            if (row < N_NODES)
                v = *(const float4*)&x[(size_t)row * IN_DIMC + kb + k4 * 4];
            *(float4*)&xs[r][k4 * 4] = v;
        }
        // ws: 64 k x 16 float4 = 1024 float4, 4 per thread
        #pragma unroll
        for (int i = 0; i < 4; i++) {
            int lin = tid + i * 256;
            int k = lin >> 4, c4 = lin & 15;
            *(float4*)&ws[k][c4 * 4] = *(const float4*)&W1[(size_t)(kb + k) * HID + c4 * 4];
        }
        __syncthreads();
        #pragma unroll 8
        for (int kk = 0; kk < 64; kk++) {
            float a[8];
            #pragma unroll
            for (int i = 0; i < 8; i++) a[i] = xs[ty * 8 + i][kk];
            float4 b = *(float4*)&ws[kk][tx * 4];
            #pragma unroll
            for (int i = 0; i < 8; i++) {
                acc[i][0] += a[i] * b.x;
                acc[i][1] += a[i] * b.y;
                acc[i][2] += a[i] * b.z;
                acc[i][3] += a[i] * b.w;
            }
        }
        __syncthreads();
    }
    #pragma unroll
    for (int i = 0; i < 8; i++) {
        int row = row0 + ty * 8 + i;
        if (row < N_NODES) {
            float d = g_dinv[row];
            float4 v = make_float4(acc[i][0] * d, acc[i][1] * d, acc[i][2] * d, acc[i][3] * d);
            size_t idx = (size_t)row * HID + tx * 4;
            *(float4*)&g_hs[idx]   = v;
            *(float4*)&g_acc1[idx] = v;   // self-loop contribution
        }
    }
}

// ---------------- scatter layer 1: acc1[tgt] += hs[src], 64 dims ----------------
__global__ void k_scatter1(const int* __restrict__ ei) {
    int tid = blockIdx.x * blockDim.x + threadIdx.x;   // E*16
    int e = tid >> 4, c = tid & 15;
    int s = clampN(__ldg(&ei[e]));
    int t = clampN(__ldg(&ei[E_EDGES + e]));
    float4 v = *(const float4*)&g_hs[(size_t)s * HID + c * 4];
    red_add_v4(&g_acc1[(size_t)t * HID + c * 4], v);
}

// ---------------- GEMM2: zs = (relu(acc1*dinv+b1) @ W2) * dinv[row]; acc2 = zs ----
// block: 64 rows x 32 cols, threads (8,16), 4x4 micro-tile, K=64 one chunk
// relu fused into the tile load (h1 never materialized)
__global__ void k_gemm2(const float* __restrict__ W2, const float* __restrict__ b1) {
    __shared__ float hsm[64][68];
    __shared__ float wsm[64][36];
    int row0 = blockIdx.x * 64;
    int tx = threadIdx.x, ty = threadIdx.y;
    int tid = ty * 8 + tx;                    // 128 threads
    float acc[4][4] = {};

    #pragma unroll
    for (int i = 0; i < 8; i++) {
        int lin = tid + i * 128;
        int r = lin >> 4, k4 = lin & 15;
        float4 v = make_float4(0.f, 0.f, 0.f, 0.f);
        int row = row0 + r;
        if (row < N_NODES) {
            float d = g_dinv[row];
            float4 a  = *(const float4*)&g_acc1[(size_t)row * HID + k4 * 4];
            float4 bb = *(const float4*)&b1[k4 * 4];
            v.x = fmaxf(a.x * d + bb.x, 0.f);
            v.y = fmaxf(a.y * d + bb.y, 0.f);
            v.z = fmaxf(a.z * d + bb.z, 0.f);
            v.w = fmaxf(a.w * d + bb.w, 0.f);
        }
        *(float4*)&hsm[r][k4 * 4] = v;
    }
    #pragma unroll
    for (int i = 0; i < 4; i++) {
        int lin = tid + i * 128;
        int k = lin >> 3, c4 = lin & 7;
        float4 v = *(const float4*)&W2[(size_t)k * EMB + c4 * 4];
        *(float4*)&wsm[k][c4 * 4] = v;
    }
    __syncthreads();
    #pragma unroll 16
    for (int kk = 0; kk < 64; kk++) {
        float a[4];
        #pragma unroll
        for (int i = 0; i < 4; i++) a[i] = hsm[ty * 4 + i][kk];
        float4 b = *(float4*)&wsm[kk][tx * 4];
        #pragma unroll
        for (int i = 0; i < 4; i++) {
            acc[i][0] += a[i] * b.x;
            acc[i][1] += a[i] * b.y;
            acc[i][2] += a[i] * b.z;
            acc[i][3] += a[i] * b.w;
        }
    }
    #pragma unroll
    for (int i = 0; i < 4; i++) {
        int row = row0 + ty * 4 + i;
        if (row < N_NODES) {
            float d = g_dinv[row];
            float4 v = make_float4(acc[i][0] * d, acc[i][1] * d, acc[i][2] * d, acc[i][3] * d);
            size_t idx = (size_t)row * EMB + tx * 4;
            *(float4*)&g_zs[idx]   = v;
            *(float4*)&g_acc2[idx] = v;
        }
    }
}

// ---------------- scatter layer 2: acc2[tgt] += zs[src], 32 dims ----------------
__global__ void k_scatter2(const int* __restrict__ ei) {
    int tid = blockIdx.x * blockDim.x + threadIdx.x;   // E*8
    int e = tid >> 3, c = tid & 7;
    int s = clampN(__ldg(&ei[e]));
    int t = clampN(__ldg(&ei[E_EDGES + e]));
    float4 v = *(const float4*)&g_zs[(size_t)s * EMB + c * 4];
    red_add_v4(&g_acc2[(size_t)t * EMB + c * 4], v);
}

// ---------------- final z: z = dinv*acc2 + b2 -> d_out ----------------
__global__ void k_z(const float* __restrict__ b2, float* __restrict__ z_out) {
    int idx = blockIdx.x * blockDim.x + threadIdx.x;   // N*8 float4s
    int row = idx >> 3, c = idx & 7;
    float d = g_dinv[row];
    float4 a = *(const float4*)&g_acc2[(size_t)idx * 4];
    float4 bb = *(const float4*)&b2[c * 4];
    float4 o = make_float4(a.x * d + bb.x, a.y * d + bb.y, a.z * d + bb.z, a.w * d + bb.w);
    *(float4*)&z_out[(size_t)idx * 4] = o;
}

// ---------------- decode: recon[e] = dot(z[src], z[tgt]) ----------------
__global__ void k_decode(const int* __restrict__ ei,
                         const float* __restrict__ z, float* __restrict__ recon) {
    int tid = blockIdx.x * blockDim.x + threadIdx.x;   // E*8
    int e = tid >> 3, c = tid & 7;
    int s = clampN(__ldg(&ei[e]));
    int t = clampN(__ldg(&ei[E_EDGES + e]));
    float4 a = *(const float4*)&z[(size_t)s * EMB + c * 4];
    float4 b = *(const float4*)&z[(size_t)t * EMB + c * 4];
    float p = a.x * b.x + a.y * b.y + a.z * b.z + a.w * b.w;
    p += __shfl_down_sync(0xffffffffu, p, 4);
    p += __shfl_down_sync(0xffffffffu, p, 2);
    p += __shfl_down_sync(0xffffffffu, p, 1);
    if (c == 0) recon[e] = p;
}

// ---------------- launch ----------------
extern "C" void kernel_launch(void* const* d_in, const int* in_sizes, int n_in,
                              void* d_out, int out_size) {
    const float* x  = (const float*)d_in[0];
    const float* W1 = (const float*)d_in[1];
    const float* b1 = (const float*)d_in[2];
    const float* W2 = (const float*)d_in[3];
    const float* b2 = (const float*)d_in[4];
    const int*   ei = (const int*)d_in[5];
    float* z_out = (float*)d_out;                          // N*EMB
    float* recon = (float*)d_out + (size_t)N_NODES * EMB;  // E

    k_init_deg<<<(N_NODES + 255) / 256, 256>>>();
    k_edges<<<E_EDGES / 256, 256>>>(ei);
    k_dinv<<<(N_NODES + 255) / 256, 256>>>();

    k_gemm1<<<(N_NODES + 127) / 128, dim3(16, 16)>>>(x, W1);
    k_scatter1<<<(E_EDGES * 16) / 256, 256>>>(ei);

    k_gemm2<<<(N_NODES + 63) / 64, dim3(8, 16)>>>(W2, b1);
    k_scatter2<<<(E_EDGES * 8) / 256, 256>>>(ei);
    k_z<<<(N_NODES * 8) / 256, 256>>>(b2, z_out);

    k_decode<<<(E_EDGES * 8) / 256, 256>>>(ei, z_out, recon);
}

// round 9
// speedup vs baseline: 1.1088x; 1.1088x over previous
#include <cuda_runtime.h>

#define N_NODES 100000
#define E_EDGES 1600000
#define IN_DIMC 128
#define HID 64
#define EMB 32

// ---------------- device scratch (no allocations allowed) ----------------
__device__ int   g_deg[N_NODES];
__device__ float g_dinv[N_NODES];
__device__ float g_hs  [(size_t)N_NODES * HID];  // (x@W1) * dinv[row]
__device__ float g_acc1[(size_t)N_NODES * HID];  // scatter accumulator L1
__device__ float g_zs  [(size_t)N_NODES * EMB];  // (h1@W2) * dinv[row]
__device__ float g_acc2[(size_t)N_NODES * EMB];  // scatter accumulator L2

// one-instruction 16B global f32 reduction (sm_90+)
__device__ __forceinline__ void red_add_v4(float* addr, float4 v) {
    asm volatile("red.global.add.v4.f32 [%0], {%1, %2, %3, %4};"
                 :: "l"(addr), "f"(v.x), "f"(v.y), "f"(v.z), "f"(v.w)
                 : "memory");
}

__device__ __forceinline__ int clampN(int v) {
    return ((unsigned)v >= N_NODES) ? 0 : v;   // defensive: rel_err not crash
}

// packed fp32x2 helpers (sm_100+; SASS FFMA2 — PTX-only, ptxas won't auto-fuse)
__device__ __forceinline__ unsigned long long dupf(float a) {
    unsigned long long r;
    asm("mov.b64 %0, {%1, %1};" : "=l"(r) : "f"(a));
    return r;
}
__device__ __forceinline__ void fma2(unsigned long long& d,
                                     unsigned long long a, unsigned long long b) {
    asm("fma.rn.f32x2 %0, %1, %2, %0;" : "+l"(d) : "l"(a), "l"(b));
}
__device__ __forceinline__ float2 unpk(unsigned long long v) {
    float lo, hi;
    asm("mov.b64 {%0, %1}, %2;" : "=f"(lo), "=f"(hi) : "l"(v));
    return make_float2(lo, hi);
}

// ---------------- degree / dinv prep ----------------
__global__ void k_init_deg() {
    int i = blockIdx.x * blockDim.x + threadIdx.x;
    if (i < N_NODES) g_deg[i] = 1;  // self-loop
}

__global__ void k_edges(const int* __restrict__ ei) {
    int i = blockIdx.x * blockDim.x + threadIdx.x;
    if (i < E_EDGES) {
        int t = clampN(ei[E_EDGES + i]);
        atomicAdd(&g_deg[t], 1);
    }
}

__global__ void k_dinv() {
    int i = blockIdx.x * blockDim.x + threadIdx.x;
    if (i < N_NODES) g_dinv[i] = rsqrtf((float)g_deg[i]);
}

// ---------------- GEMM1: hs = (x @ W1) * dinv[row]; acc1 = hs ----------------
// R3 geometry: tile 64x64, threads (16,16), 4x4 micro-tile — packed f32x2 math
__global__ void k_gemm1(const float* __restrict__ x, const float* __restrict__ W1) {
    __shared__ float xs[64][68];
    __shared__ float ws[64][68];
    int row0 = blockIdx.x * 64;
    int tx = threadIdx.x, ty = threadIdx.y;
    int tid = ty * 16 + tx;
    unsigned long long acc[4][2] = {};   // 4 rows x 2 col-pairs

    for (int kb = 0; kb < IN_DIMC; kb += 64) {
        #pragma unroll
        for (int i = 0; i < 4; i++) {
            int lin = tid + i * 256;          // 1024 float4 units
            int r = lin >> 4, k4 = lin & 15;
            float4 v = make_float4(0.f, 0.f, 0.f, 0.f);
            int row = row0 + r;
            if (row < N_NODES)
                v = *(const float4*)&x[(size_t)row * IN_DIMC + kb + k4 * 4];
            *(float4*)&xs[r][k4 * 4] = v;
        }
        #pragma unroll
        for (int i = 0; i < 4; i++) {
            int lin = tid + i * 256;
            int k = lin >> 4, c4 = lin & 15;
            *(float4*)&ws[k][c4 * 4] = *(const float4*)&W1[(size_t)(kb + k) * HID + c4 * 4];
        }
        __syncthreads();
        #pragma unroll 8
        for (int kk = 0; kk < 64; kk++) {
            ulonglong2 b = *(const ulonglong2*)&ws[kk][tx * 4];  // LDS.128, 2 packed pairs
            #pragma unroll
            for (int i = 0; i < 4; i++) {
                unsigned long long aa = dupf(xs[ty * 4 + i][kk]);
                fma2(acc[i][0], aa, b.x);
                fma2(acc[i][1], aa, b.y);
            }
        }
        __syncthreads();
    }
    #pragma unroll
    for (int i = 0; i < 4; i++) {
        int row = row0 + ty * 4 + i;
        if (row < N_NODES) {
            float d = g_dinv[row];
            float2 p0 = unpk(acc[i][0]);
            float2 p1 = unpk(acc[i][1]);
            float4 v = make_float4(p0.x * d, p0.y * d, p1.x * d, p1.y * d);
            size_t idx = (size_t)row * HID + tx * 4;
            *(float4*)&g_hs[idx]   = v;
            *(float4*)&g_acc1[idx] = v;   // self-loop contribution
        }
    }
}

// ---------------- scatter layer 1: acc1[tgt] += hs[src], 64 dims ----------------
__global__ void k_scatter1(const int* __restrict__ ei) {
    int tid = blockIdx.x * blockDim.x + threadIdx.x;   // E*16
    int e = tid >> 4, c = tid & 15;
    int s = clampN(__ldg(&ei[e]));
    int t = clampN(__ldg(&ei[E_EDGES + e]));
    float4 v = *(const float4*)&g_hs[(size_t)s * HID + c * 4];
    red_add_v4(&g_acc1[(size_t)t * HID + c * 4], v);
}

// ---------------- GEMM2: zs = (relu(acc1*dinv+b1) @ W2) * dinv[row]; acc2 = zs ----
// block: 64 rows x 32 cols, threads (8,16), 4x4 micro-tile, K=64 — packed f32x2
__global__ void k_gemm2(const float* __restrict__ W2, const float* __restrict__ b1) {
    __shared__ float hsm[64][68];
    __shared__ float wsm[64][36];
    int row0 = blockIdx.x * 64;
    int tx = threadIdx.x, ty = threadIdx.y;
    int tid = ty * 8 + tx;                    // 128 threads
    unsigned long long acc[4][2] = {};

    #pragma unroll
    for (int i = 0; i < 8; i++) {
        int lin = tid + i * 128;
        int r = lin >> 4, k4 = lin & 15;
        float4 v = make_float4(0.f, 0.f, 0.f, 0.f);
        int row = row0 + r;
        if (row < N_NODES) {
            float d = g_dinv[row];
            float4 a  = *(const float4*)&g_acc1[(size_t)row * HID + k4 * 4];
            float4 bb = *(const float4*)&b1[k4 * 4];
            v.x = fmaxf(a.x * d + bb.x, 0.f);
            v.y = fmaxf(a.y * d + bb.y, 0.f);
            v.z = fmaxf(a.z * d + bb.z, 0.f);
            v.w = fmaxf(a.w * d + bb.w, 0.f);
        }
        *(float4*)&hsm[r][k4 * 4] = v;
    }
    #pragma unroll
    for (int i = 0; i < 4; i++) {
        int lin = tid + i * 128;
        int k = lin >> 3, c4 = lin & 7;
        float4 v = *(const float4*)&W2[(size_t)k * EMB + c4 * 4];
        *(float4*)&wsm[k][c4 * 4] = v;
    }
    __syncthreads();
    #pragma unroll 8
    for (int kk = 0; kk < 64; kk++) {
        ulonglong2 b = *(const ulonglong2*)&wsm[kk][tx * 4];   // LDS.128
        #pragma unroll
        for (int i = 0; i < 4; i++) {
            unsigned long long aa = dupf(hsm[ty * 4 + i][kk]);
            fma2(acc[i][0], aa, b.x);
            fma2(acc[i][1], aa, b.y);
        }
    }
    #pragma unroll
    for (int i = 0; i < 4; i++) {
        int row = row0 + ty * 4 + i;
        if (row < N_NODES) {
            float d = g_dinv[row];
            float2 p0 = unpk(acc[i][0]);
            float2 p1 = unpk(acc[i][1]);
            float4 v = make_float4(p0.x * d, p0.y * d, p1.x * d, p1.y * d);
            size_t idx = (size_t)row * EMB + tx * 4;
            *(float4*)&g_zs[idx]   = v;
            *(float4*)&g_acc2[idx] = v;
        }
    }
}

// ---------------- scatter layer 2: acc2[tgt] += zs[src], 32 dims ----------------
__global__ void k_scatter2(const int* __restrict__ ei) {
    int tid = blockIdx.x * blockDim.x + threadIdx.x;   // E*8
    int e = tid >> 3, c = tid & 7;
    int s = clampN(__ldg(&ei[e]));
    int t = clampN(__ldg(&ei[E_EDGES + e]));
    float4 v = *(const float4*)&g_zs[(size_t)s * EMB + c * 4];
    red_add_v4(&g_acc2[(size_t)t * EMB + c * 4], v);
}

// ---------------- final z: z = dinv*acc2 + b2 -> d_out ----------------
__global__ void k_z(const float* __restrict__ b2, float* __restrict__ z_out) {
    int idx = blockIdx.x * blockDim.x + threadIdx.x;   // N*8 float4s
    int row = idx >> 3, c = idx & 7;
    float d = g_dinv[row];
    float4 a = *(const float4*)&g_acc2[(size_t)idx * 4];
    float4 bb = *(const float4*)&b2[c * 4];
    float4 o = make_float4(a.x * d + bb.x, a.y * d + bb.y, a.z * d + bb.z, a.w * d + bb.w);
    *(float4*)&z_out[(size_t)idx * 4] = o;
}

// ---------------- decode: recon[e] = dot(z[src], z[tgt]) ----------------
__global__ void k_decode(const int* __restrict__ ei,
                         const float* __restrict__ z, float* __restrict__ recon) {
    int tid = blockIdx.x * blockDim.x + threadIdx.x;   // E*8
    int e = tid >> 3, c = tid & 7;
    int s = clampN(__ldg(&ei[e]));
    int t = clampN(__ldg(&ei[E_EDGES + e]));
    float4 a = *(const float4*)&z[(size_t)s * EMB + c * 4];
    float4 b = *(const float4*)&z[(size_t)t * EMB + c * 4];
    float p = a.x * b.x + a.y * b.y + a.z * b.z + a.w * b.w;
    p += __shfl_down_sync(0xffffffffu, p, 4);
    p += __shfl_down_sync(0xffffffffu, p, 2);
    p += __shfl_down_sync(0xffffffffu, p, 1);
    if (c == 0) recon[e] = p;
}

// ---------------- launch ----------------
extern "C" void kernel_launch(void* const* d_in, const int* in_sizes, int n_in,
                              void* d_out, int out_size) {
    const float* x  = (const float*)d_in[0];
    const float* W1 = (const float*)d_in[1];
    const float* b1 = (const float*)d_in[2];
    const float* W2 = (const float*)d_in[3];
    const float* b2 = (const float*)d_in[4];
    const int*   ei = (const int*)d_in[5];
    float* z_out = (float*)d_out;                          // N*EMB
    float* recon = (float*)d_out + (size_t)N_NODES * EMB;  // E

    k_init_deg<<<(N_NODES + 255) / 256, 256>>>();
    k_edges<<<E_EDGES / 256, 256>>>(ei);
    k_dinv<<<(N_NODES + 255) / 256, 256>>>();

    k_gemm1<<<(N_NODES + 63) / 64, dim3(16, 16)>>>(x, W1);
    k_scatter1<<<(E_EDGES * 16) / 256, 256>>>(ei);

    k_gemm2<<<(N_NODES + 63) / 64, dim3(8, 16)>>>(W2, b1);
    k_scatter2<<<(E_EDGES * 8) / 256, 256>>>(ei);
    k_z<<<(N_NODES * 8) / 256, 256>>>(b2, z_out);

    k_decode<<<(E_EDGES * 8) / 256, 256>>>(ei, z_out, recon);
}